// round 1
// baseline (speedup 1.0000x reference)
#include <cuda_runtime.h>

#define INN   40
#define HID   16384
#define OUTN  22
#define FAN0  8192
#define FAN1  11
#define THRESH 0.3f

// Scratch (allocation-free rule: __device__ globals)
__device__ float g_add_h[HID];
__device__ float g_add_o[OUTN];

// K0: zero the scratch accumulators (graph replays need fresh zeros each run)
__global__ void k0_zero() {
    int n = blockIdx.x * blockDim.x + threadIdx.x;
    if (n < HID)  g_add_h[n] = 0.0f;
    if (n < OUTN) g_add_o[n] = 0.0f;
}

// K1: input -> hidden scatter at t=0.
// One thread per fan-out column j; loop over the 40 inputs. The spike check is
// warp-uniform, so rows with spike==0 (~90%) issue zero memory traffic.
__global__ void k1_in_scatter(const float* __restrict__ spikes,
                              const float* __restrict__ w0,
                              const int*   __restrict__ tgt0) {
    int j = blockIdx.x * blockDim.x + threadIdx.x;
    if (j >= FAN0) return;
#pragma unroll 1
    for (int i = 0; i < INN; ++i) {
        float s = 2.0f * spikes[i];          // spk_in = input_spikes * 2
        if (s != 0.0f) {
            float w = w0[i * FAN0 + j];
            int   t = tgt0[i * FAN0 + j];
            atomicAdd(&g_add_h[t], s * w);
        }
    }
}

// K2: hidden threshold at t=0 + hidden -> output scatter (lands at t=1).
// Writes the masked post-t0 hidden potential (add_h*decay, 0 if spiked)
// directly into the pot_h region of d_out; K3 scales it in place.
__global__ void k2_hidden(const float* __restrict__ w1,
                          const int*   __restrict__ tgt1,
                          float* __restrict__ out,   // full output buffer
                          float decay) {
    __shared__ float sacc[OUTN];
    int tid = threadIdx.x;
    if (tid < OUTN) sacc[tid] = 0.0f;
    __syncthreads();

    int i = blockIdx.x * blockDim.x + tid;
    if (i < HID) {
        float a = g_add_h[i] * decay;        // pot_h at end of t=0
        bool  s = (a >= THRESH);             // hidden spike (only possible at t=0)
        out[2 * OUTN + i] = s ? 0.0f : a;    // masked potential, pre-scaling
        if (s) {
#pragma unroll
            for (int j = 0; j < FAN1; ++j) {
                atomicAdd(&sacc[tgt1[i * FAN1 + j]], w1[i * FAN1 + j]);
            }
        }
    }
    __syncthreads();
    if (tid < OUTN) atomicAdd(&g_add_o[tid], sacc[tid]);
}

// K3: finalize. Compute fired mask / all_fired, pick S (early-break emulation),
// apply decay^(S-1) to pot_o and (in place) to pot_h, write out_t.
// Layout of out (float32): [0:22) out_t, [22:44) pot_o, [44:44+HID) pot_h.
__global__ void k3_final(float* __restrict__ out,
                         const int* __restrict__ mt_p,
                         float decay) {
    int n = blockIdx.x * blockDim.x + threadIdx.x;
    if (n >= HID + OUTN) return;

    int  mt        = mt_p[0];
    bool out_phase = (mt >= 2);              // t=1 must exist for outputs to fire

    bool all_f = out_phase;
#pragma unroll
    for (int o = 0; o < OUTN; ++o)
        all_f = all_f && (g_add_o[o] * decay >= THRESH);

    // steps actually simulated before freeze
    int S = all_f ? 2 : mt;
    // fac = decay^(S-1)
    float fac = 1.0f;
    for (int k = 1; k < S; ++k) fac *= decay;

    if (n < OUTN) {
        float ao = g_add_o[n];
        bool  f  = out_phase && (ao * decay >= THRESH);   // fires at t=1 or never
        out[n]        = f ? 1.0f : -1.0f;                 // out_t
        out[OUTN + n] = out_phase ? ao * fac : 0.0f;      // pot_o = add_o * decay^(S-1)
    } else {
        int i = n - OUTN;
        // pot_h = masked(add_h*decay) * decay^(S-1) = masked * decay^S
        out[2 * OUTN + i] = (mt >= 1) ? out[2 * OUTN + i] * fac : 0.0f;
    }
}

extern "C" void kernel_launch(void* const* d_in, const int* in_sizes, int n_in,
                              void* d_out, int out_size) {
    const float* spikes = (const float*)d_in[0];   // (40,)
    const float* w0     = (const float*)d_in[1];   // (40, 8192)
    const int*   tgt0   = (const int*)  d_in[2];   // (40, 8192)
    const float* w1     = (const float*)d_in[3];   // (16384, 11)
    const int*   tgt1   = (const int*)  d_in[4];   // (16384, 11)
    const int*   mt     = (const int*)  d_in[5];   // scalar max_timesteps
    float* out = (float*)d_out;                    // 22 + 22 + 16384 floats

    const float decay = expf(-1.0f / 20.0f);

    k0_zero      <<<(HID + 255) / 256, 256>>>();
    k1_in_scatter<<<(FAN0 + 255) / 256, 256>>>(spikes, w0, tgt0);
    k2_hidden    <<<(HID + 255) / 256, 256>>>(w1, tgt1, out, decay);
    k3_final     <<<(HID + OUTN + 255) / 256, 256>>>(out, mt, decay);
}

// round 2
// speedup vs baseline: 1.1025x; 1.1025x over previous
#include <cuda_runtime.h>

#define INN   40
#define HID   16384
#define OUTN  22
#define FAN0  8192
#define FAN1  11
#define THRESH 0.3f
#define NBLK  64
#define NTHR  256
#define NWARP (NTHR / 32)
#define DECAY 0.95122942450071400910f   // float32(exp(-1/20))

// Scratch — __device__ globals (allocation-free rule). Zero-initialized at
// module load; every execution restores them to all-zero before it ends
// (zero-on-consume), so graph replays see a clean state.
__device__ float    g_add_h[HID];
__device__ float    g_add_o[OUTN];
__device__ unsigned g_bar = 0;   // arrival counter (returns to 0 every sync)
__device__ unsigned g_gen = 0;   // generation (monotonic; spinners snapshot it)

__device__ __forceinline__ void grid_sync() {
    __syncthreads();
    if (threadIdx.x == 0) {
        __threadfence();                                   // release my block's writes
        unsigned gen = *(volatile unsigned*)&g_gen;
        if (atomicAdd(&g_bar, 1u) == NBLK - 1u) {
            atomicExch(&g_bar, 0u);
            __threadfence();
            atomicExch(&g_gen, gen + 1u);                  // open the gate
        } else {
            while (*(volatile unsigned*)&g_gen == gen) { } // spin on L2
        }
        __threadfence();                                   // acquire
    }
    __syncthreads();
}

__global__ __launch_bounds__(NTHR, 1)
void snn_fused(const float* __restrict__ spikes,
               const float* __restrict__ w0,
               const int*   __restrict__ tgt0,
               const float* __restrict__ w1,
               const int*   __restrict__ tgt1,
               const int*   __restrict__ mt_p,
               float*       __restrict__ out)
{
    __shared__ float s_spk[INN];
    __shared__ float s_bins[NWARP][24];   // warp-private output bins (22 used, stride 24)
    __shared__ float s_ao[OUTN];
    __shared__ int   s_allf;

    const int tid = threadIdx.x;
    const int gid = blockIdx.x * NTHR + tid;   // 0..16383, one hidden neuron each
    const int wrp = tid >> 5;
    const int lan = tid & 31;

    // ── Phase A (block-local): stage spikes, zero bins, block 0 zeroes g_add_o
    if (tid < INN) s_spk[tid] = 2.0f * spikes[tid];        // spk_in = input*2
    if (lan < 24)  s_bins[wrp][lan] = 0.0f;
    if (blockIdx.x == 0 && tid < OUTN) g_add_o[tid] = 0.0f;
    __syncthreads();

    // ── Phase B: input -> hidden scatter (t=0). Threads gid < FAN0.
    // g_add_h is guaranteed all-zero here (zero-init / zero-on-consume).
    if (gid < FAN0) {
#pragma unroll 1
        for (int i = 0; i < INN; ++i) {
            float s = s_spk[i];                 // uniform branch: ~90% rows skipped
            if (s != 0.0f) {
                atomicAdd(&g_add_h[tgt0[i * FAN0 + gid]], s * w0[i * FAN0 + gid]);
            }
        }
    }

    grid_sync();   // all scatter contributions visible

    // ── Phase C: hidden threshold (only possible at t=0) + hidden -> output scatter
    float a = g_add_h[gid] * DECAY;             // pot_h at end of t=0
    g_add_h[gid] = 0.0f;                        // zero-on-consume for next replay
    bool  sp = (a >= THRESH);
    float pot_reg = sp ? 0.0f : a;              // masked potential, held in register
    if (sp) {
        const float* wr = w1   + gid * FAN1;
        const int*   tr = tgt1 + gid * FAN1;
#pragma unroll
        for (int j = 0; j < FAN1; ++j)
            atomicAdd(&s_bins[wrp][tr[j]], wr[j]);
    }
    __syncthreads();
    if (tid < OUTN) {
        float v = 0.0f;
#pragma unroll
        for (int w = 0; w < NWARP; ++w) v += s_bins[w][tid];
        if (v != 0.0f) atomicAdd(&g_add_o[tid], v);
    }

    grid_sync();   // all output contributions visible

    // ── Phase D: finalize. Outputs can only fire at t=1; early-break => S=2.
    const int  mt        = mt_p[0];
    const bool out_phase = (mt >= 2);

    if (tid < 32) {
        float ao = (tid < OUTN) ? g_add_o[tid] : 0.0f;
        if (tid < OUTN) s_ao[tid] = ao;
        bool f = (tid >= OUTN) || (ao * DECAY >= THRESH);
        unsigned m = __ballot_sync(0xffffffffu, f);
        if (tid == 0) s_allf = (m == 0xffffffffu);
    }
    __syncthreads();

    const bool all_f = out_phase && s_allf;
    const int  S     = all_f ? 2 : mt;          // steps simulated before freeze
    float fac = 1.0f;                           // decay^(S-1), ref rounding pattern
    for (int k = 1; k < S; ++k) fac *= DECAY;

    // out layout (float32): [0:22) out_t, [22:44) pot_o, [44:44+HID) pot_h
    out[2 * OUTN + gid] = (mt >= 1) ? pot_reg * fac : 0.0f;   // pot_h = masked*decay^S
    if (blockIdx.x == 0 && tid < OUTN) {
        float ao = s_ao[tid];
        bool  f  = out_phase && (ao * DECAY >= THRESH);
        out[tid]        = f ? 1.0f : -1.0f;                   // out_t (fires at t=1 or never)
        out[OUTN + tid] = out_phase ? ao * fac : 0.0f;        // pot_o = add_o*decay^(S-1)
    }
}

extern "C" void kernel_launch(void* const* d_in, const int* in_sizes, int n_in,
                              void* d_out, int out_size) {
    const float* spikes = (const float*)d_in[0];   // (40,)
    const float* w0     = (const float*)d_in[1];   // (40, 8192)
    const int*   tgt0   = (const int*)  d_in[2];   // (40, 8192)
    const float* w1     = (const float*)d_in[3];   // (16384, 11)
    const int*   tgt1   = (const int*)  d_in[4];   // (16384, 11)
    const int*   mt     = (const int*)  d_in[5];   // scalar max_timesteps
    float* out = (float*)d_out;

    snn_fused<<<NBLK, NTHR>>>(spikes, w0, tgt0, w1, tgt1, mt, out);
}

// round 3
// speedup vs baseline: 1.2335x; 1.1189x over previous
#include <cuda_runtime.h>

#define INN   40
#define HID   16384
#define OUTN  22
#define FAN0  8192
#define FAN1  11
#define THRESH 0.3f
#define NBLK  64
#define NTHR  256
#define NWARP (NTHR / 32)
#define DECAY 0.95122942450071400910f   // float32(exp(-1/20))

// Scratch — __device__ globals (allocation-free rule). Zero-initialized at load;
// every execution restores them to zero before it ends (zero-on-consume), so
// graph replays see a clean state.
__device__ float g_add_h[HID];
__device__ float g_add_o[OUTN];
// Barrier words on separate 128B lines: spinner polls must not contend with
// the arrival atomics at the LTS atomic ALU.
__device__ __align__(128) unsigned g_bar[32];   // [0] used, rest padding
__device__ __align__(128) unsigned g_gen[32];   // [0] used, rest padding

__device__ __forceinline__ void grid_sync() {
    __syncthreads();
    if (threadIdx.x == 0) {
        __threadfence();                                      // release
        unsigned gen = *(volatile unsigned*)&g_gen[0];
        if (atomicAdd(&g_bar[0], 1u) == NBLK - 1u) {
            *(volatile unsigned*)&g_bar[0] = 0u;              // all arrived; safe
            __threadfence();
            atomicExch(&g_gen[0], gen + 1u);                  // open gate
        } else {
            while (*(volatile unsigned*)&g_gen[0] == gen) { }
        }
        __threadfence();                                      // acquire
    }
    __syncthreads();
}

__global__ __launch_bounds__(NTHR, 1)
void snn_fused(const float* __restrict__ spikes,
               const float* __restrict__ w0,
               const int*   __restrict__ tgt0,
               const float* __restrict__ w1,
               const int*   __restrict__ tgt1,
               const int*   __restrict__ mt_p,
               float*       __restrict__ out)
{
    __shared__ float s_actv[INN];         // compact active-input values (2*spike)
    __shared__ int   s_acti[INN];         // compact active-input indices
    __shared__ int   s_cnt;
    __shared__ float s_bins[NWARP][24];   // warp-private output bins (22 used)
    __shared__ float s_ao[32];
    __shared__ int   s_allf;

    const int tid = threadIdx.x;
    const int gid = blockIdx.x * NTHR + tid;   // 0..16383 — one hidden neuron
    const int wrp = tid >> 5;
    const int lan = tid & 31;

    // ── Prefetch (issued first; consumed only after barrier 1): my neuron's
    // w1/tgt1 row into registers, plus mt. Latency overlaps phases A+B+bar1.
    float w1r[FAN1];
    int   t1r[FAN1];
    {
        const float* wr = w1   + gid * FAN1;
        const int*   tr = tgt1 + gid * FAN1;
#pragma unroll
        for (int j = 0; j < FAN1; ++j) { w1r[j] = __ldg(wr + j); t1r[j] = __ldg(tr + j); }
    }
    const int mt = __ldg(mt_p);

    // ── Phase A: compact active-input list, zero bins, block0 zeroes g_add_o
    if (tid == 0) s_cnt = 0;
    if (lan < 24) s_bins[wrp][lan] = 0.0f;
    if (blockIdx.x == 0 && tid < OUTN) g_add_o[tid] = 0.0f;   // ordered vs. phase C by bar1
    __syncthreads();
    if (tid < INN) {
        float s = 2.0f * spikes[tid];            // spk_in = input*2 (nonzero only t=0)
        if (s != 0.0f) {
            int p = atomicAdd(&s_cnt, 1);
            s_acti[p] = tid;
            s_actv[p] = s;
        }
    }
    __syncthreads();
    const int cnt = s_cnt;

    // ── Phase B: input -> hidden scatter (t=0). Two threads per fan column:
    // thread pair (j, j+8192) splits active inputs even/odd — halves the chain.
    {
        const int j    = gid & (FAN0 - 1);
        const int half = gid >> 13;              // 0 or 1
#pragma unroll 1
        for (int k = half; k < cnt; k += 2) {
            const int   off = s_acti[k] * FAN0 + j;
            atomicAdd(&g_add_h[tgt0[off]], s_actv[k] * w0[off]);
        }
    }

    grid_sync();   // all hidden contributions visible

    // ── Phase C: hidden threshold (only possible at t=0) + hidden -> output
    float a = g_add_h[gid] * DECAY;              // pot_h at end of t=0
    g_add_h[gid] = 0.0f;                         // zero-on-consume for next replay
    const bool  sp  = (a >= THRESH);
    const float pot = sp ? 0.0f : a;             // masked potential (register)
    if (sp) {
#pragma unroll
        for (int j = 0; j < FAN1; ++j)
            atomicAdd(&s_bins[wrp][t1r[j]], w1r[j]);   // prefetched — no loads here
    }
    __syncthreads();
    if (tid < OUTN) {
        float v = 0.0f;
#pragma unroll
        for (int w = 0; w < NWARP; ++w) v += s_bins[w][tid];
        if (v != 0.0f) atomicAdd(&g_add_o[tid], v);
    }

    grid_sync();   // all output contributions visible

    // ── Phase D: finalize. Outputs can only fire at t=1; early-break => S=2.
    const bool out_phase = (mt >= 2);
    if (tid < 32) {
        float ao = (tid < OUTN) ? g_add_o[tid] : 0.0f;
        s_ao[tid] = ao;
        bool f = (tid >= OUTN) || (ao * DECAY >= THRESH);
        unsigned m = __ballot_sync(0xffffffffu, f);
        if (tid == 0) s_allf = (m == 0xffffffffu);
    }
    __syncthreads();

    const bool all_f = out_phase && s_allf;
    const int  S     = all_f ? 2 : mt;           // steps simulated before freeze
    float fac = 1.0f;
    for (int k = 1; k < S; ++k) fac *= DECAY;    // decay^(S-1)

    // out layout (float32): [0:22) out_t, [22:44) pot_o, [44:44+HID) pot_h
    out[2 * OUTN + gid] = (mt >= 1) ? pot * fac : 0.0f;       // pot_h = masked*decay^S
    if (blockIdx.x == 0 && tid < OUTN) {
        float ao = s_ao[tid];
        bool  f  = out_phase && (ao * DECAY >= THRESH);
        out[tid]        = f ? 1.0f : -1.0f;                   // out_t: t=1 or never
        out[OUTN + tid] = out_phase ? ao * fac : 0.0f;        // pot_o = add_o*decay^(S-1)
    }
}

extern "C" void kernel_launch(void* const* d_in, const int* in_sizes, int n_in,
                              void* d_out, int out_size) {
    const float* spikes = (const float*)d_in[0];   // (40,)
    const float* w0     = (const float*)d_in[1];   // (40, 8192)
    const int*   tgt0   = (const int*)  d_in[2];   // (40, 8192)
    const float* w1     = (const float*)d_in[3];   // (16384, 11)
    const int*   tgt1   = (const int*)  d_in[4];   // (16384, 11)
    const int*   mt     = (const int*)  d_in[5];   // scalar max_timesteps
    float* out = (float*)d_out;

    snn_fused<<<NBLK, NTHR>>>(spikes, w0, tgt0, w1, tgt1, mt, out);
}

// round 4
// speedup vs baseline: 1.2630x; 1.0239x over previous
#include <cuda_runtime.h>

#define INN   40
#define HID   16384
#define OUTN  22
#define FAN0  8192
#define FAN1  11
#define THRESH 0.3f
#define NBLK  128
#define NTHR  128
#define NWARP (NTHR / 32)
#define ROWS  NTHR                       // hidden rows per block
#define V4N   ((ROWS * FAN1) / 4)        // 352 float4 per array per block
#define DECAY 0.95122942450071400910f    // float32(exp(-1/20))

// Scratch — __device__ globals (allocation-free rule). Zero-init at load; each
// execution restores zeros (zero-on-consume) so graph replays see clean state.
__device__ float g_add_h[HID];
__device__ float g_add_o[OUTN];
// Barrier state: per-block gen-stamped flags (distinct words, parallel STG
// arrivals) + a generation word the spinners poll. Monotonic across replays.
__device__ __align__(128) unsigned g_flag[NBLK];
__device__ __align__(128) unsigned g_gen[32];

// Flag barrier: all blocks STG flag=gen+1; block 0's warp 0 polls all flags
// (4 per lane), then bumps g_gen. Cumulative fences carry write visibility.
__device__ __forceinline__ void grid_sync() {
    __syncthreads();
    if (threadIdx.x < 32) {
        const unsigned gen = *(volatile unsigned*)&g_gen[0];
        if (threadIdx.x == 0) {
            __threadfence();                                  // release block's writes
            *(volatile unsigned*)&g_flag[blockIdx.x] = gen + 1u;
        }
        if (blockIdx.x == 0) {
            const int b = threadIdx.x * 4;
            for (;;) {
                bool ok = (*(volatile unsigned*)&g_flag[b]     == gen + 1u)
                        & (*(volatile unsigned*)&g_flag[b + 1] == gen + 1u)
                        & (*(volatile unsigned*)&g_flag[b + 2] == gen + 1u)
                        & (*(volatile unsigned*)&g_flag[b + 3] == gen + 1u);
                if (__all_sync(0xffffffffu, ok)) break;
            }
            if (threadIdx.x == 0) {
                __threadfence();                              // order polls before release
                *(volatile unsigned*)&g_gen[0] = gen + 1u;
            }
        } else if (threadIdx.x == 0) {
            while (*(volatile unsigned*)&g_gen[0] == gen) { }
            __threadfence();                                  // acquire
        }
    }
    __syncthreads();
}

__global__ __launch_bounds__(NTHR, 1)
void snn_fused(const float* __restrict__ spikes,
               const float* __restrict__ w0,
               const int*   __restrict__ tgt0,
               const float* __restrict__ w1,
               const int*   __restrict__ tgt1,
               const int*   __restrict__ mt_p,
               float*       __restrict__ out)
{
    __shared__ float s_w1[ROWS * FAN1];   // staged w1 slice (1408 floats)
    __shared__ int   s_t1[ROWS * FAN1];   // staged tgt1 slice
    __shared__ float s_actv[INN];         // compact active-input values (2*spike)
    __shared__ int   s_acti[INN];
    __shared__ int   s_cnt;
    __shared__ float s_bins[NWARP][24];   // warp-private output bins (22 used)
    __shared__ float s_ao[32];
    __shared__ int   s_allf;

    const int tid = threadIdx.x;
    const int gid = blockIdx.x * NTHR + tid;   // one hidden neuron per thread
    const int wrp = tid >> 5;
    const int lan = tid & 31;

    const int mt = __ldg(mt_p);

    // ── Phase A: compact active inputs, zero bins, block0 zeroes g_add_o
    if (tid == 0) s_cnt = 0;
    if (lan < 24) s_bins[wrp][lan] = 0.0f;
    if (blockIdx.x == 0 && tid < OUTN) g_add_o[tid] = 0.0f;   // ordered by bar1
    __syncthreads();
    if (tid < INN) {
        float s = 2.0f * spikes[tid];            // spk_in = input*2 (t=0 only)
        if (s != 0.0f) {
            int p = atomicAdd(&s_cnt, 1);
            s_acti[p] = tid;
            s_actv[p] = s;
        }
    }
    __syncthreads();
    const int cnt = s_cnt;

    // ── Phase B: input -> hidden scatter (t=0), 2 threads per fan column,
    // batched loads (MLP=4) so ~4 active inputs cost one DRAM round trip.
    {
        const int j    = gid & (FAN0 - 1);
        const int half = gid >> 13;              // 0 or 1
#pragma unroll 1
        for (int k = half; k < cnt; k += 4) {
            const bool h1   = (k + 2) < cnt;
            const int  off0 = s_acti[k] * FAN0 + j;
            const int  off1 = h1 ? s_acti[k + 2] * FAN0 + j : off0;
            const int   t0 = tgt0[off0];
            const float a0 = w0[off0];
            const int   t1 = tgt0[off1];
            const float a1 = w0[off1];
            atomicAdd(&g_add_h[t0], s_actv[k] * a0);
            if (h1) atomicAdd(&g_add_h[t1], s_actv[k + 2] * a1);
        }
    }

    // ── Stage this block's w1/tgt1 slice into shared with LDG.128 (4x fewer
    // LSU issues than per-thread scalar rows). Issued after phase B's atomics;
    // DRAM latency overlaps the barrier-1 wait. Consumed after grid_sync.
    {
        const float4* wv = (const float4*)(w1   + blockIdx.x * (ROWS * FAN1));
        const int4*   tv = (const int4*)  (tgt1 + blockIdx.x * (ROWS * FAN1));
        float4* sw = (float4*)s_w1;
        int4*   st = (int4*)s_t1;
#pragma unroll
        for (int i = 0; i < (V4N + NTHR - 1) / NTHR; ++i) {
            const int idx = tid + i * NTHR;
            if (idx < V4N) { sw[idx] = __ldg(wv + idx); st[idx] = __ldg(tv + idx); }
        }
    }

    grid_sync();   // all hidden contributions visible (+ staging STS ordered)

    // ── Phase C: hidden threshold (only possible at t=0) + hidden -> output
    float a = g_add_h[gid] * DECAY;              // pot_h at end of t=0
    g_add_h[gid] = 0.0f;                         // zero-on-consume for replay
    const bool  sp  = (a >= THRESH);
    const float pot = sp ? 0.0f : a;
    if (sp) {
        const int base = tid * FAN1;
#pragma unroll
        for (int j = 0; j < FAN1; ++j)
            atomicAdd(&s_bins[wrp][s_t1[base + j]], s_w1[base + j]);
    }
    __syncthreads();
    if (tid < OUTN) {
        float v = 0.0f;
#pragma unroll
        for (int w = 0; w < NWARP; ++w) v += s_bins[w][tid];
        if (v != 0.0f) atomicAdd(&g_add_o[tid], v);
    }

    grid_sync();   // all output contributions visible

    // ── Phase D: finalize. Outputs can only fire at t=1; early-break => S=2.
    const bool out_phase = (mt >= 2);
    if (tid < 32) {
        float ao = (tid < OUTN) ? g_add_o[tid] : 0.0f;
        s_ao[tid] = ao;
        bool f = (tid >= OUTN) || (ao * DECAY >= THRESH);
        unsigned m = __ballot_sync(0xffffffffu, f);
        if (tid == 0) s_allf = (m == 0xffffffffu);
    }
    __syncthreads();

    const bool all_f = out_phase && s_allf;
    const int  S     = all_f ? 2 : mt;           // steps simulated before freeze
    float fac = 1.0f;
    for (int k = 1; k < S; ++k) fac *= DECAY;    // decay^(S-1)

    // out layout (float32): [0:22) out_t, [22:44) pot_o, [44:44+HID) pot_h
    out[2 * OUTN + gid] = (mt >= 1) ? pot * fac : 0.0f;       // pot_h = masked*decay^S
    if (blockIdx.x == 0 && tid < OUTN) {
        float ao = s_ao[tid];
        bool  f  = out_phase && (ao * DECAY >= THRESH);
        out[tid]        = f ? 1.0f : -1.0f;                   // out_t: t=1 or never
        out[OUTN + tid] = out_phase ? ao * fac : 0.0f;        // pot_o = add_o*decay^(S-1)
    }
}

extern "C" void kernel_launch(void* const* d_in, const int* in_sizes, int n_in,
                              void* d_out, int out_size) {
    const float* spikes = (const float*)d_in[0];   // (40,)
    const float* w0     = (const float*)d_in[1];   // (40, 8192)
    const int*   tgt0   = (const int*)  d_in[2];   // (40, 8192)
    const float* w1     = (const float*)d_in[3];   // (16384, 11)
    const int*   tgt1   = (const int*)  d_in[4];   // (16384, 11)
    const int*   mt     = (const int*)  d_in[5];   // scalar max_timesteps
    float* out = (float*)d_out;

    snn_fused<<<NBLK, NTHR>>>(spikes, w0, tgt0, w1, tgt1, mt, out);
}

// round 5
// speedup vs baseline: 1.4525x; 1.1500x over previous
#include <cuda_runtime.h>

#define INN   40
#define HID   16384
#define OUTN  22
#define FAN0  8192
#define FAN1  11
#define THRESH 0.3f
#define NBLK  64
#define NTHR  256
#define NWARP (NTHR / 32)
#define DECAY 0.95122942450071400910f   // float32(exp(-1/20))

// Scratch — __device__ globals (allocation-free rule). g_add_h / g_add_o are
// zero at load and restored to zero by every execution (zero-on-consume), so
// graph replays see a clean state. Sync words are MONOTONIC (never reset):
// replay r does sync ids 2r (barrier) and 2r+1 (publish).
__device__ float g_add_h[HID];
__device__ float g_add_o[OUTN];
__device__ __align__(128) unsigned g_bar[32];   // [0]: monotonic arrival counter
__device__ __align__(128) unsigned g_gen[32];   // [0]: barrier-1 generation
__device__ __align__(128) unsigned g_pub[32];   // [0]: payload (id<<1 | all_f)

__global__ __launch_bounds__(NTHR, 1)
void snn_fused(const float* __restrict__ spikes,
               const float* __restrict__ w0,
               const int*   __restrict__ tgt0,
               const float* __restrict__ w1,
               const int*   __restrict__ tgt1,
               const int*   __restrict__ mt_p,
               float*       __restrict__ out)
{
    __shared__ float s_actv[INN];
    __shared__ int   s_acti[INN];
    __shared__ int   s_cnt;
    __shared__ float s_bins[NWARP][24];   // warp-private output bins (22 used)
    __shared__ int   s_fin;               // 1 iff this block is the finisher
    __shared__ int   s_allf;

    const int tid = threadIdx.x;
    const int gid = blockIdx.x * NTHR + tid;   // one hidden neuron per thread
    const int wrp = tid >> 5;
    const int lan = tid & 31;

    // ── Prefetch (issued first, consumed after barrier 1): my w1/tgt1 row.
    float w1r[FAN1];
    int   t1r[FAN1];
    {
        const float* wr = w1   + gid * FAN1;
        const int*   tr = tgt1 + gid * FAN1;
#pragma unroll
        for (int j = 0; j < FAN1; ++j) { w1r[j] = __ldg(wr + j); t1r[j] = __ldg(tr + j); }
    }
    const int mt = __ldg(mt_p);
    const unsigned gen = *(volatile unsigned*)&g_gen[0];   // == replay index r

    // ── Phase A: compact active inputs, zero bins
    if (tid == 0) { s_cnt = 0; s_fin = 0; }
    if (lan < 24) s_bins[wrp][lan] = 0.0f;
    __syncthreads();
    if (tid < INN) {
        float s = 2.0f * spikes[tid];             // spk_in = input*2 (t=0 only)
        if (s != 0.0f) {
            int p = atomicAdd(&s_cnt, 1);
            s_acti[p] = tid;
            s_actv[p] = s;
        }
    }
    __syncthreads();
    const int cnt = s_cnt;

    // ── Phase B: input -> hidden scatter (t=0). 2 threads per fan column,
    // loads batched ahead of the atomics (MLP).
    {
        const int j    = gid & (FAN0 - 1);
        const int half = gid >> 13;               // 0 or 1
#pragma unroll 1
        for (int k = half; k < cnt; k += 4) {
            const bool h1   = (k + 2) < cnt;
            const int  off0 = s_acti[k] * FAN0 + j;
            const int  off1 = h1 ? s_acti[k + 2] * FAN0 + j : off0;
            const int   t0 = tgt0[off0];
            const float a0 = w0[off0];
            const int   t1 = tgt0[off1];
            const float a1 = w0[off1];
            atomicAdd(&g_add_h[t0], s_actv[k] * a0);
            if (h1) atomicAdd(&g_add_h[t1], s_actv[k + 2] * a1);
        }
    }

    // ── Barrier 1 (monotonic counter; last arriver releases directly)
    __syncthreads();
    if (tid == 0) {
        __threadfence();                                       // release
        unsigned old = atomicAdd(&g_bar[0], 1u);
        if (old == (2u * gen + 1u) * NBLK - 1u) {
            *(volatile unsigned*)&g_gen[0] = gen + 1u;         // open gate
        } else {
            while (*(volatile unsigned*)&g_gen[0] == gen) { }
        }
        __threadfence();                                       // acquire
    }
    __syncthreads();

    // ── Phase C: hidden threshold (only possible at t=0) + hidden -> output
    float a = g_add_h[gid] * DECAY;               // pot_h at end of t=0
    g_add_h[gid] = 0.0f;                          // zero-on-consume for replay
    const bool  sp  = (a >= THRESH);
    const float pot = sp ? 0.0f : a;              // masked potential (register)
    if (sp) {
#pragma unroll
        for (int j = 0; j < FAN1; ++j)
            atomicAdd(&s_bins[wrp][t1r[j]], w1r[j]);   // prefetched, no loads
    }
    __syncthreads();

    // ── Post partials + publish-sync. Finisher = last block to arrive.
    if (tid < 32) {
        if (tid < OUTN) {
            float v = 0.0f;
#pragma unroll
            for (int w = 0; w < NWARP; ++w) v += s_bins[w][tid];
            if (v != 0.0f) atomicAdd(&g_add_o[tid], v);
        }
        __threadfence();                           // my REDGs visible pre-arrival
        if (tid == 0) {
            unsigned old = atomicAdd(&g_bar[0], 1u);
            if (old == (2u * gen + 2u) * NBLK - 1u) s_fin = 1;
        }
    }
    __syncthreads();

    const bool out_phase = (mt >= 2);              // outputs fire at t=1 or never

    if (s_fin) {
        // Finisher: read totals, compute all_f, write out_t/pot_o, publish.
        float ao = 0.0f;
        if (tid < 32) {
            if (tid < OUTN) {
                ao = g_add_o[tid];                 // all REDGs fenced-in by arrivals
                g_add_o[tid] = 0.0f;               // zero-on-consume for replay
            }
            bool f = (tid >= OUTN) || (ao * DECAY >= THRESH);
            unsigned m = __ballot_sync(0xffffffffu, f);
            if (tid == 0) {
                int allf = out_phase && (m == 0xffffffffu);
                s_allf = allf;
                __threadfence();                   // order g_add_o zeroing too
                *(volatile unsigned*)&g_pub[0] = ((gen + 1u) << 1) | (unsigned)allf;
            }
        }
        __syncthreads();
        const int S = s_allf ? 2 : mt;
        float fac = 1.0f;
        for (int k = 1; k < S; ++k) fac *= DECAY;  // decay^(S-1)
        if (tid < OUTN) {
            bool f = out_phase && (ao * DECAY >= THRESH);
            out[tid]        = f ? 1.0f : -1.0f;                // out_t
            out[OUTN + tid] = out_phase ? ao * fac : 0.0f;     // pot_o
        }
        out[2 * OUTN + gid] = (mt >= 1) ? pot * fac : 0.0f;    // pot_h
    } else {
        // Non-finisher: spin on the single payload word, then write pot_h.
        if (tid == 0) {
            unsigned v;
            while (((v = *(volatile unsigned*)&g_pub[0]) >> 1) != gen + 1u) { }
            s_allf = (int)(v & 1u);
        }
        __syncthreads();
        const int S = s_allf ? 2 : mt;
        float fac = 1.0f;
        for (int k = 1; k < S; ++k) fac *= DECAY;
        out[2 * OUTN + gid] = (mt >= 1) ? pot * fac : 0.0f;    // pot_h
    }
}

extern "C" void kernel_launch(void* const* d_in, const int* in_sizes, int n_in,
                              void* d_out, int out_size) {
    const float* spikes = (const float*)d_in[0];   // (40,)
    const float* w0     = (const float*)d_in[1];   // (40, 8192)
    const int*   tgt0   = (const int*)  d_in[2];   // (40, 8192)
    const float* w1     = (const float*)d_in[3];   // (16384, 11)
    const int*   tgt1   = (const int*)  d_in[4];   // (16384, 11)
    const int*   mt     = (const int*)  d_in[5];   // scalar max_timesteps
    float* out = (float*)d_out;

    snn_fused<<<NBLK, NTHR>>>(spikes, w0, tgt0, w1, tgt1, mt, out);
}